// round 11
// baseline (speedup 1.0000x reference)
#include <cuda_runtime.h>
#include <cstdint>

#define HDIM 4096
#define VOCAB 50257
#define SEQL 2048
#define TOPK 50
#define MINKEEP 5
#define NVBLK ((VOCAB + 255) / 256)     // 197
#define CAP 4096
#define BMW ((VOCAB + 31) / 32)

__device__ float g_mu;
__device__ float g_rstd;
__device__ float g_logits[VOCAB];
__device__ unsigned int g_coarse[1024];
__device__ unsigned int g_bitmap[BMW];
__device__ unsigned int g_Bf;
__device__ int g_cnt;
__device__ float g_cv[CAP];
__device__ int   g_ci[CAP];

__device__ __forceinline__ unsigned int fkey(float f) {
    unsigned int u = __float_as_uint(f);
    return (u & 0x80000000u) ? ~u : (u | 0x80000000u);
}

// ------- prep: LN scalars + penalty bitmap + coarse-hist/counter resets (one block) -------
__global__ void __launch_bounds__(1024) prep_kernel(const float* __restrict__ hin,
                                                    const void* __restrict__ ids_raw) {
    __shared__ float ws[32];
    __shared__ float sh_mu;
    __shared__ int bad;
    int tid = threadIdx.x;
    int lane = tid & 31, warp = tid >> 5;

    for (int i = tid; i < BMW; i += 1024) g_bitmap[i] = 0u;
    g_coarse[tid] = 0u;
    if (tid == 0) { bad = 0; g_cnt = 0; }

    float4 h = ((const float4*)hin)[tid];
    float s = (h.x + h.y) + (h.z + h.w);
#pragma unroll
    for (int o = 16; o > 0; o >>= 1) s += __shfl_down_sync(0xffffffffu, s, o);
    if (lane == 0) ws[warp] = s;
    __syncthreads();
    if (warp == 0) {
        float t = ws[lane];
#pragma unroll
        for (int o = 16; o > 0; o >>= 1) t += __shfl_down_sync(0xffffffffu, t, o);
        if (lane == 0) sh_mu = t / HDIM;
    }
    __syncthreads();
    float mu = sh_mu;

    float dx = h.x - mu, dy = h.y - mu, dz = h.z - mu, dw = h.w - mu;
    float q = (dx * dx + dy * dy) + (dz * dz + dw * dw);
#pragma unroll
    for (int o = 16; o > 0; o >>= 1) q += __shfl_down_sync(0xffffffffu, q, o);
    if (lane == 0) ws[warp] = q;
    __syncthreads();
    if (warp == 0) {
        float t = ws[lane];
#pragma unroll
        for (int o = 16; o > 0; o >>= 1) t += __shfl_down_sync(0xffffffffu, t, o);
        if (lane == 0) { g_mu = mu; g_rstd = rsqrtf(t / HDIM + 1e-5f); }
    }

    // ---- int64-vs-int32 detection (first 8KB valid under both) ----
    const long long* ll = (const long long*)ids_raw;
    long long probe = ll[tid];
    if (probe < 0 || probe >= VOCAB) atomicOr(&bad, 1);
    __syncthreads();
    int is64 = (bad == 0);
    long long id0, id1;
    if (is64) { id0 = ll[tid]; id1 = ll[tid + 1024]; }
    else {
        const int* ii = (const int*)ids_raw;
        id0 = ii[tid]; id1 = ii[tid + 1024];
    }
    atomicOr(&g_bitmap[(int)(id0 >> 5)], 1u << ((int)id0 & 31));
    atomicOr(&g_bitmap[(int)(id1 >> 5)], 1u << ((int)id1 & 31));
}

// ------- GEMV full-H per thread: LN inline, penalty + logit + smem coarse hist in epilogue -------
__global__ void __launch_bounds__(256) gemv_kernel(const float* __restrict__ W,
                                                   const float* __restrict__ hin,
                                                   const float* __restrict__ gamma,
                                                   const float* __restrict__ beta,
                                                   const float* __restrict__ pen) {
    __shared__ float xs[HDIM];
    __shared__ unsigned sh_hist[1024];
    int tid = threadIdx.x;
    for (int i = tid; i < 1024; i += 256) sh_hist[i] = 0u;
    float mu = g_mu, rstd = g_rstd;
    for (int i = tid; i < HDIM; i += 256)
        xs[i] = (hin[i] - mu) * rstd * gamma[i] + beta[i];
    __syncthreads();

    int v = blockIdx.x * 256 + tid;
    bool act = (v < VOCAB);
    float r = 0.f;
    if (act) {
        const float* wp = W + v;
        float a0 = 0.f, a1 = 0.f, a2 = 0.f, a3 = 0.f;
        for (int i = 0; i < HDIM; i += 32) {
            float w[32];
#pragma unroll
            for (int j = 0; j < 32; j++) w[j] = __ldcs(wp + (size_t)j * VOCAB);
            wp += 32 * (size_t)VOCAB;
#pragma unroll
            for (int j = 0; j < 32; j += 4) {
                a0 += xs[i + j]     * w[j];
                a1 += xs[i + j + 1] * w[j + 1];
                a2 += xs[i + j + 2] * w[j + 2];
                a3 += xs[i + j + 3] * w[j + 3];
            }
        }
        r = (a0 + a1) + (a2 + a3);
        if ((g_bitmap[v >> 5] >> (v & 31)) & 1u) {
            float p = pen[0];
            r = (r < 0.f) ? r * p : r / p;
        }
        g_logits[v] = r;
        atomicAdd(&sh_hist[fkey(r) >> 22], 1u);
    }
    __syncthreads();
    for (int i = tid; i < 1024; i += 256) {
        unsigned c = sh_hist[i];
        if (c) atomicAdd(&g_coarse[i], c);
    }
}

// ------- threshold: coarse-only (1024 bins) -------
__global__ void thresh_kernel() {
    __shared__ unsigned cs[1024];
    __shared__ unsigned ws[32];
    int tid = threadIdx.x;
    unsigned c = g_coarse[tid];
    cs[tid] = c;
    unsigned s = c;
    for (int o = 16; o > 0; o >>= 1) s += __shfl_down_sync(0xffffffffu, s, o);
    if ((tid & 31) == 0) ws[tid >> 5] = s;
    __syncthreads();
    if (tid == 0) {
        unsigned acc = 0;
        int w = 31;
        for (; w > 0; --w) {
            if (acc + ws[w] >= (unsigned)TOPK) break;
            acc += ws[w];
        }
        int B = w * 32;
        for (int b = w * 32 + 31; b >= w * 32; --b) {
            unsigned cc = cs[b];
            if (acc + cc >= (unsigned)TOPK) { B = b; break; }
            acc += cc;
        }
        g_Bf = (unsigned)B << 22;
    }
}

// ------- parallel candidate collection (threshold = coarse bin start) -------
__global__ void collect_kernel() {
    int v = blockIdx.x * 256 + threadIdx.x;
    if (v >= VOCAB) return;
    float f = g_logits[v];
    if (fkey(f) >= g_Bf) {
        int p = atomicAdd(&g_cnt, 1);
        if (p < CAP) { g_cv[p] = f; g_ci[p] = v; }
    }
}

// ------- rank-sort (n up to ~CAP) + temperature/top-p sampling -------
__global__ void __launch_bounds__(1024) sort_sample_kernel(
        const float* __restrict__ tp_,
        const float* __restrict__ temp_,
        float* __restrict__ out, int out_size) {
    __shared__ float cv[CAP];
    __shared__ int   ci[CAP];
    __shared__ float tv[TOPK];
    __shared__ int   tix[TOPK];
    __shared__ float sx[TOPK];
    __shared__ float sp[TOPK];
    int tid = threadIdx.x;
    int n = min(g_cnt, CAP);
    for (int i = tid; i < n; i += 1024) { cv[i] = g_cv[i]; ci[i] = g_ci[i]; }
    __syncthreads();
    for (int i = tid; i < n; i += 1024) {
        float v = cv[i]; int ix = ci[i];
        int r = 0;
        for (int j = 0; j < n; j++) {
            float vj = cv[j];
            if (vj > v || (vj == v && ci[j] < ix)) r++;
        }
        if (r < TOPK) { tv[r] = v; tix[r] = ix; }
    }
    __syncthreads();
    if (tid < TOPK) sx[tid] = tv[tid] / temp_[0];
    __syncthreads();
    if (tid < TOPK) sp[tid] = expf(sx[tid] - sx[0]);
    __syncthreads();
    if (tid == 0) {
        float tp = tp_[0];
        float m = sx[0];
        float s = 0.f;
        for (int i = 0; i < TOPK; i++) s += sp[i];
        float cum = 0.f, s2 = 0.f;
        for (int i = 0; i < TOPK; i++) {
            cum += sp[i] / s;
            bool keep = (cum < tp) || (i < MINKEEP);
            float f = keep ? sx[i] : -1000.0f;
            float e = expf(f - m);
            sp[i] = e;
            s2 += e;
        }
        sx[0] = s2;
    }
    __syncthreads();
    if (tid < TOPK) out[tid] = sp[tid] / sx[0];
    if (out_size >= 2 * TOPK && tid < TOPK) out[TOPK + tid] = (float)tix[tid];
}

extern "C" void kernel_launch(void* const* d_in, const int* in_sizes, int n_in,
                              void* d_out, int out_size) {
    const float* hidden = (const float*)d_in[0];
    const void*  ids    = d_in[1];
    const float* top_p  = (const float*)d_in[2];
    const float* temp   = (const float*)d_in[3];
    const float* pen    = (const float*)d_in[4];
    const float* gamma  = (const float*)d_in[5];
    const float* beta   = (const float*)d_in[6];
    const float* W      = (const float*)d_in[7];
    float* out = (float*)d_out;

    prep_kernel<<<1, 1024>>>(hidden, ids);
    gemv_kernel<<<NVBLK, 256>>>(W, hidden, gamma, beta, pen);
    thresh_kernel<<<1, 1024>>>();
    collect_kernel<<<NVBLK, 256>>>();
    sort_sample_kernel<<<1, 1024>>>(top_p, temp, out, out_size);
}

// round 12
// speedup vs baseline: 1.1186x; 1.1186x over previous
#include <cuda_runtime.h>
#include <cstdint>

#define HDIM 4096
#define VOCAB 50257
#define SEQL 2048
#define TOPK 50
#define MINKEEP 5
#define NVBLK ((VOCAB + 255) / 256)     // 197
#define CAP 2048
#define BMW ((VOCAB + 31) / 32)
#define TILE_COLS 32
#define NTILES ((VOCAB + TILE_COLS - 1) / TILE_COLS)   // 1571
#define NPERS (148 * 4)                                // 592 persistent blocks
#define HEIGHTH (HDIM / 8)                             // 512

__device__ float g_mu;
__device__ float g_rstd;
__device__ float g_logits[VOCAB];
__device__ unsigned int g_hist[65536];
__device__ unsigned int g_coarse[1024];
__device__ unsigned int g_bitmap[BMW];
__device__ unsigned int g_Bf;
__device__ int g_cnt;
__device__ int g_tile;
__device__ float g_cv[CAP];
__device__ int   g_ci[CAP];

__device__ __forceinline__ unsigned int fkey(float f) {
    unsigned int u = __float_as_uint(f);
    return (u & 0x80000000u) ? ~u : (u | 0x80000000u);
}

// ------- prep: LN scalars + penalty bitmap + all resets/zeroing (one block) -------
__global__ void __launch_bounds__(1024) prep_kernel(const float* __restrict__ hin,
                                                    const void* __restrict__ ids_raw) {
    __shared__ float ws[32];
    __shared__ float sh_mu;
    __shared__ int bad;
    int tid = threadIdx.x;
    int lane = tid & 31, warp = tid >> 5;

    for (int i = tid; i < 65536; i += 1024) g_hist[i] = 0u;
    g_coarse[tid] = 0u;
    for (int i = tid; i < BMW; i += 1024) g_bitmap[i] = 0u;
    if (tid == 0) { bad = 0; g_cnt = 0; g_tile = 0; }

    float4 h = ((const float4*)hin)[tid];
    float s = (h.x + h.y) + (h.z + h.w);
#pragma unroll
    for (int o = 16; o > 0; o >>= 1) s += __shfl_down_sync(0xffffffffu, s, o);
    if (lane == 0) ws[warp] = s;
    __syncthreads();
    if (warp == 0) {
        float t = ws[lane];
#pragma unroll
        for (int o = 16; o > 0; o >>= 1) t += __shfl_down_sync(0xffffffffu, t, o);
        if (lane == 0) sh_mu = t / HDIM;
    }
    __syncthreads();
    float mu = sh_mu;

    float dx = h.x - mu, dy = h.y - mu, dz = h.z - mu, dw = h.w - mu;
    float q = (dx * dx + dy * dy) + (dz * dz + dw * dw);
#pragma unroll
    for (int o = 16; o > 0; o >>= 1) q += __shfl_down_sync(0xffffffffu, q, o);
    if (lane == 0) ws[warp] = q;
    __syncthreads();
    if (warp == 0) {
        float t = ws[lane];
#pragma unroll
        for (int o = 16; o > 0; o >>= 1) t += __shfl_down_sync(0xffffffffu, t, o);
        if (lane == 0) { g_mu = mu; g_rstd = rsqrtf(t / HDIM + 1e-5f); }
    }

    // ---- int64-vs-int32 detection (first 8KB valid under both) ----
    const long long* ll = (const long long*)ids_raw;
    long long probe = ll[tid];
    if (probe < 0 || probe >= VOCAB) atomicOr(&bad, 1);
    __syncthreads();
    int is64 = (bad == 0);
    long long id0, id1;
    if (is64) { id0 = ll[tid]; id1 = ll[tid + 1024]; }
    else {
        const int* ii = (const int*)ids_raw;
        id0 = ii[tid]; id1 = ii[tid + 1024];
    }
    atomicOr(&g_bitmap[(int)(id0 >> 5)], 1u << ((int)id0 & 31));
    atomicOr(&g_bitmap[(int)(id1 >> 5)], 1u << ((int)id1 & 31));
}

// ------- persistent work-stealing GEMV: full-H per tile, fused penalty+hist epilogue -------
__global__ void __launch_bounds__(256, 4) gemv_kernel(const float* __restrict__ W,
                                                      const float* __restrict__ hin,
                                                      const float* __restrict__ gamma,
                                                      const float* __restrict__ beta,
                                                      const float* __restrict__ pen) {
    __shared__ float xs[HDIM];           // full LN'd hidden, loaded once per block
    __shared__ float red[8 * TILE_COLS];
    __shared__ int sh_tile;
    int tid = threadIdx.x;
    int c = tid & 31;                    // column within tile
    int e = tid >> 5;                    // H-eighth (0..7), == warp id

    float mu = g_mu, rstd = g_rstd;
    for (int i = tid; i < HDIM; i += 256)
        xs[i] = (hin[i] - mu) * rstd * gamma[i] + beta[i];
    float p = pen[0];
    int hbase = e * HEIGHTH;

    for (;;) {
        __syncthreads();                 // red[] free + sh_tile consumed
        if (tid == 0) sh_tile = atomicAdd(&g_tile, 1);
        __syncthreads();
        int tile = sh_tile;
        if (tile >= NTILES) break;

        int col = tile * TILE_COLS + c;
        bool act = (col < VOCAB);
        float a0 = 0.f, a1 = 0.f, a2 = 0.f, a3 = 0.f;
        if (act) {
            const float* wp = W + (size_t)hbase * VOCAB + col;
            for (int i = 0; i < HEIGHTH; i += 16) {
                float w[16];
#pragma unroll
                for (int j = 0; j < 16; j++) w[j] = __ldcs(wp + (size_t)j * VOCAB);
                wp += 16 * (size_t)VOCAB;
#pragma unroll
                for (int j = 0; j < 16; j += 4) {
                    a0 += xs[hbase + i + j]     * w[j];
                    a1 += xs[hbase + i + j + 1] * w[j + 1];
                    a2 += xs[hbase + i + j + 2] * w[j + 2];
                    a3 += xs[hbase + i + j + 3] * w[j + 3];
                }
            }
        }
        red[e * TILE_COLS + c] = (a0 + a1) + (a2 + a3);
        __syncthreads();
        if (e == 0 && act) {
            // deterministic fixed reduction tree over the 8 partials
            float r01 = red[0 * TILE_COLS + c] + red[1 * TILE_COLS + c];
            float r23 = red[2 * TILE_COLS + c] + red[3 * TILE_COLS + c];
            float r45 = red[4 * TILE_COLS + c] + red[5 * TILE_COLS + c];
            float r67 = red[6 * TILE_COLS + c] + red[7 * TILE_COLS + c];
            float r = (r01 + r23) + (r45 + r67);
            if ((g_bitmap[col >> 5] >> (col & 31)) & 1u)
                r = (r < 0.f) ? r * p : r / p;
            g_logits[col] = r;
            unsigned k = fkey(r);
            atomicAdd(&g_hist[k >> 16], 1u);
            atomicAdd(&g_coarse[k >> 22], 1u);
        }
    }
}

// ---------------- threshold: coarse scan + one 64-bin fine chunk (UNCHANGED) ----------------
__global__ void thresh_kernel() {
    __shared__ unsigned cs[1024];
    __shared__ unsigned ws[32];
    __shared__ unsigned fb[64];
    __shared__ int sh_t;
    __shared__ unsigned sh_acc;
    int tid = threadIdx.x;
    unsigned c = g_coarse[tid];
    cs[tid] = c;
    unsigned s = c;
    for (int o = 16; o > 0; o >>= 1) s += __shfl_down_sync(0xffffffffu, s, o);
    if ((tid & 31) == 0) ws[tid >> 5] = s;
    __syncthreads();
    if (tid == 0) {
        unsigned acc = 0;
        int w = 31;
        for (; w > 0; --w) {
            if (acc + ws[w] >= (unsigned)TOPK) break;
            acc += ws[w];
        }
        int t = w * 32;
        for (int b = w * 32 + 31; b >= w * 32; --b) {
            unsigned cc = cs[b];
            if (acc + cc >= (unsigned)TOPK) { t = b; break; }
            acc += cc;
        }
        sh_t = t; sh_acc = acc;
    }
    __syncthreads();
    int t = sh_t;
    if (tid < 64) fb[tid] = g_hist[t * 64 + tid];
    __syncthreads();
    if (tid == 0) {
        unsigned acc = sh_acc;
        int B = t * 64;
        for (int b = 63; b >= 0; --b) {
            unsigned cc = fb[b];
            if (acc + cc >= (unsigned)TOPK) { B = t * 64 + b; break; }
            acc += cc;
        }
        g_Bf = (unsigned)B << 16;
    }
}

// ---------------- parallel candidate collection (UNCHANGED) ----------------
__global__ void collect_kernel() {
    int v = blockIdx.x * 256 + threadIdx.x;
    if (v >= VOCAB) return;
    float f = g_logits[v];
    if (fkey(f) >= g_Bf) {
        int p = atomicAdd(&g_cnt, 1);
        if (p < CAP) { g_cv[p] = f; g_ci[p] = v; }
    }
}

// ---------------- rank-sort + sampling (UNCHANGED) ----------------
__global__ void __launch_bounds__(1024) sort_sample_kernel(
        const float* __restrict__ tp_,
        const float* __restrict__ temp_,
        float* __restrict__ out, int out_size) {
    __shared__ float cv[CAP];
    __shared__ int   ci[CAP];
    __shared__ float tv[TOPK];
    __shared__ int   tix[TOPK];
    __shared__ float sx[TOPK];
    __shared__ float sp[TOPK];
    int tid = threadIdx.x;
    int n = min(g_cnt, CAP);
    for (int i = tid; i < n; i += 1024) { cv[i] = g_cv[i]; ci[i] = g_ci[i]; }
    __syncthreads();
    for (int i = tid; i < n; i += 1024) {
        float v = cv[i]; int ix = ci[i];
        int r = 0;
        for (int j = 0; j < n; j++) {
            float vj = cv[j];
            if (vj > v || (vj == v && ci[j] < ix)) r++;
        }
        if (r < TOPK) { tv[r] = v; tix[r] = ix; }
    }
    __syncthreads();
    if (tid < TOPK) sx[tid] = tv[tid] / temp_[0];
    __syncthreads();
    if (tid < TOPK) sp[tid] = expf(sx[tid] - sx[0]);
    __syncthreads();
    if (tid == 0) {
        float tp = tp_[0];
        float m = sx[0];
        float s = 0.f;
        for (int i = 0; i < TOPK; i++) s += sp[i];
        float cum = 0.f, s2 = 0.f;
        for (int i = 0; i < TOPK; i++) {
            cum += sp[i] / s;
            bool keep = (cum < tp) || (i < MINKEEP);
            float f = keep ? sx[i] : -1000.0f;
            float e = expf(f - m);
            sp[i] = e;
            s2 += e;
        }
        sx[0] = s2;
    }
    __syncthreads();
    if (tid < TOPK) out[tid] = sp[tid] / sx[0];
    if (out_size >= 2 * TOPK && tid < TOPK) out[TOPK + tid] = (float)tix[tid];
}

extern "C" void kernel_launch(void* const* d_in, const int* in_sizes, int n_in,
                              void* d_out, int out_size) {
    const float* hidden = (const float*)d_in[0];
    const void*  ids    = d_in[1];
    const float* top_p  = (const float*)d_in[2];
    const float* temp   = (const float*)d_in[3];
    const float* pen    = (const float*)d_in[4];
    const float* gamma  = (const float*)d_in[5];
    const float* beta   = (const float*)d_in[6];
    const float* W      = (const float*)d_in[7];
    float* out = (float*)d_out;

    prep_kernel<<<1, 1024>>>(hidden, ids);
    gemv_kernel<<<NPERS, 256>>>(W, hidden, gamma, beta, pen);
    thresh_kernel<<<1, 1024>>>();
    collect_kernel<<<NVBLK, 256>>>();
    sort_sample_kernel<<<1, 1024>>>(top_p, temp, out, out_size);
}

// round 13
// speedup vs baseline: 1.2966x; 1.1592x over previous
#include <cuda_runtime.h>
#include <cstdint>

#define HDIM 4096
#define VOCAB 50257
#define SEQL 2048
#define TOPK 50
#define MINKEEP 5
#define HSPLIT 4
#define HCHUNK (HDIM / HSPLIT)          // 1024
#define NVBLK ((VOCAB + 255) / 256)     // 197
#define CAP 4096
#define BMW ((VOCAB + 31) / 32)

__device__ float g_part[HSPLIT * VOCAB];
__device__ float g_logits[VOCAB];
__device__ unsigned int g_coarse[1024];
__device__ unsigned int g_bitmap[BMW];
__device__ unsigned int g_Bf;
__device__ int g_cnt;
__device__ float g_cv[CAP];
__device__ int   g_ci[CAP];

__device__ __forceinline__ unsigned int fkey(float f) {
    unsigned int u = __float_as_uint(f);
    return (u & 0x80000000u) ? ~u : (u | 0x80000000u);
}

// ------- GEMV: per-block LN stats (redundant, deterministic) + inline LN + 16-in-flight stream.
//         Block (0,0) additionally builds the penalty bitmap (consumed by fuse, next kernel). -------
__global__ void __launch_bounds__(256, 6) gemv_kernel(const float* __restrict__ W,
                                                      const float* __restrict__ hin,
                                                      const float* __restrict__ gamma,
                                                      const float* __restrict__ beta,
                                                      const void* __restrict__ ids_raw) {
    __shared__ float ws[8];
    __shared__ float sh_mu, sh_rstd;
    __shared__ float xs[HCHUNK];
    __shared__ int bad;
    int tid = threadIdx.x;
    int lane = tid & 31, warp = tid >> 5;
    int hb = blockIdx.y;
    int h0 = hb * HCHUNK;

    // zero coarse hist (consumed by fuse, a later kernel — strictly ordered)
    int gb = (hb * gridDim.x + blockIdx.x) * 256 + tid;
    if (gb < 1024) g_coarse[gb] = 0u;

    // ---- per-block LN statistics over full H (deterministic fixed tree) ----
    float4 h4[4];
#pragma unroll
    for (int k = 0; k < 4; k++) h4[k] = ((const float4*)hin)[tid + k * 256];
    float s = 0.f;
#pragma unroll
    for (int k = 0; k < 4; k++) s += (h4[k].x + h4[k].y) + (h4[k].z + h4[k].w);
#pragma unroll
    for (int o = 16; o > 0; o >>= 1) s += __shfl_down_sync(0xffffffffu, s, o);
    if (lane == 0) ws[warp] = s;
    __syncthreads();
    if (tid == 0) {
        float t = ((ws[0] + ws[1]) + (ws[2] + ws[3])) + ((ws[4] + ws[5]) + (ws[6] + ws[7]));
        sh_mu = t / HDIM;
    }
    __syncthreads();
    float mu = sh_mu;
    float q = 0.f;
#pragma unroll
    for (int k = 0; k < 4; k++) {
        float dx = h4[k].x - mu, dy = h4[k].y - mu, dz = h4[k].z - mu, dw = h4[k].w - mu;
        q += (dx * dx + dy * dy) + (dz * dz + dw * dw);
    }
#pragma unroll
    for (int o = 16; o > 0; o >>= 1) q += __shfl_down_sync(0xffffffffu, q, o);
    if (lane == 0) ws[warp] = q;
    __syncthreads();
    if (tid == 0) {
        float t = ((ws[0] + ws[1]) + (ws[2] + ws[3])) + ((ws[4] + ws[5]) + (ws[6] + ws[7]));
        sh_rstd = rsqrtf(t / HDIM + 1e-5f);
    }
    __syncthreads();
    float rstd = sh_rstd;

    // ---- block (0,0): penalty bitmap (zero + int64/int32 detect + build) ----
    if (blockIdx.x == 0 && hb == 0) {
        for (int i = tid; i < BMW; i += 256) g_bitmap[i] = 0u;
        if (tid == 0) bad = 0;
        __syncthreads();
        const long long* ll = (const long long*)ids_raw;
        int myBad = 0;
#pragma unroll
        for (int j = 0; j < 4; j++) {              // probe first 8KB only (safe both ways)
            long long p = ll[tid + j * 256];
            if (p < 0 || p >= VOCAB) myBad = 1;
        }
        if (myBad) atomicOr(&bad, 1);
        __syncthreads();
        int is64 = (bad == 0);
        if (is64) {
#pragma unroll
            for (int j = 0; j < 8; j++) {
                long long id = ll[tid + j * 256];
                atomicOr(&g_bitmap[(int)(id >> 5)], 1u << ((int)id & 31));
            }
        } else {
            const int* ii = (const int*)ids_raw;
#pragma unroll
            for (int j = 0; j < 8; j++) {
                int id = ii[tid + j * 256];
                atomicOr(&g_bitmap[id >> 5], 1u << (id & 31));
            }
        }
    }

    // ---- stage LN'd chunk, then stream (UNCHANGED core) ----
    for (int i = tid; i < HCHUNK; i += 256)
        xs[i] = (hin[h0 + i] - mu) * rstd * gamma[h0 + i] + beta[h0 + i];
    __syncthreads();
    int v = blockIdx.x * 256 + tid;
    if (v >= VOCAB) return;
    const float* wp = W + (size_t)h0 * VOCAB + v;
    float a0 = 0.f, a1 = 0.f, a2 = 0.f, a3 = 0.f;
    for (int i = 0; i < HCHUNK; i += 16) {
        float w[16];
#pragma unroll
        for (int j = 0; j < 16; j++) w[j] = __ldcs(wp + (size_t)j * VOCAB);
        wp += 16 * (size_t)VOCAB;
#pragma unroll
        for (int j = 0; j < 16; j += 4) {
            a0 += xs[i + j]     * w[j];
            a1 += xs[i + j + 1] * w[j + 1];
            a2 += xs[i + j + 2] * w[j + 2];
            a3 += xs[i + j + 3] * w[j + 3];
        }
    }
    g_part[hb * VOCAB + v] = (a0 + a1) + (a2 + a3);
}

// ---------------- combine + penalty + coarse histogram only ----------------
__global__ void fuse_kernel(const float* __restrict__ pen) {
    int v = blockIdx.x * 256 + threadIdx.x;
    if (v >= VOCAB) return;
    float s = (g_part[v] + g_part[VOCAB + v]) +
              (g_part[2 * VOCAB + v] + g_part[3 * VOCAB + v]);
    if ((g_bitmap[v >> 5] >> (v & 31)) & 1u) {
        float p = pen[0];
        s = (s < 0.f) ? s * p : s / p;
    }
    g_logits[v] = s;
    atomicAdd(&g_coarse[fkey(s) >> 22], 1u);
}

// ---------------- threshold: coarse-only (validated in R11); also resets g_cnt ----------------
__global__ void thresh_kernel() {
    __shared__ unsigned cs[1024];
    __shared__ unsigned ws[32];
    int tid = threadIdx.x;
    unsigned c = g_coarse[tid];
    cs[tid] = c;
    unsigned s = c;
    for (int o = 16; o > 0; o >>= 1) s += __shfl_down_sync(0xffffffffu, s, o);
    if ((tid & 31) == 0) ws[tid >> 5] = s;
    __syncthreads();
    if (tid == 0) {
        unsigned acc = 0;
        int w = 31;
        for (; w > 0; --w) {
            if (acc + ws[w] >= (unsigned)TOPK) break;
            acc += ws[w];
        }
        int B = w * 32;
        for (int b = w * 32 + 31; b >= w * 32; --b) {
            unsigned cc = cs[b];
            if (acc + cc >= (unsigned)TOPK) { B = b; break; }
            acc += cc;
        }
        g_Bf = (unsigned)B << 22;
        g_cnt = 0;
    }
}

// ---------------- parallel candidate collection ----------------
__global__ void collect_kernel() {
    int v = blockIdx.x * 256 + threadIdx.x;
    if (v >= VOCAB) return;
    float f = g_logits[v];
    if (fkey(f) >= g_Bf) {
        int p = atomicAdd(&g_cnt, 1);
        if (p < CAP) { g_cv[p] = f; g_ci[p] = v; }
    }
}

// ---------------- rank-sort (n up to CAP) + temperature/top-p sampling ----------------
__global__ void __launch_bounds__(1024) sort_sample_kernel(
        const float* __restrict__ tp_,
        const float* __restrict__ temp_,
        float* __restrict__ out, int out_size) {
    __shared__ float cv[CAP];
    __shared__ int   ci[CAP];
    __shared__ float tv[TOPK];
    __shared__ int   tix[TOPK];
    __shared__ float sx[TOPK];
    __shared__ float sp[TOPK];
    int tid = threadIdx.x;
    int n = min(g_cnt, CAP);
    for (int i = tid; i < n; i += 1024) { cv[i] = g_cv[i]; ci[i] = g_ci[i]; }
    __syncthreads();
    for (int i = tid; i < n; i += 1024) {
        float v = cv[i]; int ix = ci[i];
        int r = 0;
        for (int j = 0; j < n; j++) {
            float vj = cv[j];
            if (vj > v || (vj == v && ci[j] < ix)) r++;
        }
        if (r < TOPK) { tv[r] = v; tix[r] = ix; }
    }
    __syncthreads();
    if (tid < TOPK) sx[tid] = tv[tid] / temp_[0];
    __syncthreads();
    if (tid < TOPK) sp[tid] = expf(sx[tid] - sx[0]);
    __syncthreads();
    if (tid == 0) {
        float tp = tp_[0];
        float m = sx[0];
        float s = 0.f;
        for (int i = 0; i < TOPK; i++) s += sp[i];
        float cum = 0.f, s2 = 0.f;
        for (int i = 0; i < TOPK; i++) {
            cum += sp[i] / s;
            bool keep = (cum < tp) || (i < MINKEEP);
            float f = keep ? sx[i] : -1000.0f;
            float e = expf(f - m);
            sp[i] = e;
            s2 += e;
        }
        sx[0] = s2;
    }
    __syncthreads();
    if (tid < TOPK) out[tid] = sp[tid] / sx[0];
    if (out_size >= 2 * TOPK && tid < TOPK) out[TOPK + tid] = (float)tix[tid];
}

extern "C" void kernel_launch(void* const* d_in, const int* in_sizes, int n_in,
                              void* d_out, int out_size) {
    const float* hidden = (const float*)d_in[0];
    const void*  ids    = d_in[1];
    const float* top_p  = (const float*)d_in[2];
    const float* temp   = (const float*)d_in[3];
    const float* pen    = (const float*)d_in[4];
    const float* gamma  = (const float*)d_in[5];
    const float* beta   = (const float*)d_in[6];
    const float* W      = (const float*)d_in[7];
    float* out = (float*)d_out;

    dim3 g(NVBLK, HSPLIT);
    gemv_kernel<<<g, 256>>>(W, hidden, gamma, beta, ids);
    fuse_kernel<<<NVBLK, 256>>>(pen);
    thresh_kernel<<<1, 1024>>>();
    collect_kernel<<<NVBLK, 256>>>();
    sort_sample_kernel<<<1, 1024>>>(top_p, temp, out, out_size);
}